// round 1
// baseline (speedup 1.0000x reference)
#include <cuda_runtime.h>

#define B_   2048
#define T_   128
#define I_   130
#define H_   10
#define G3   30          // 3*H
#define ROWS (B_ * T_)   // 262144
#define CHUNK 26         // 130 = 5 * 26
#define TPB  256

// Scratch (static device globals: allocation-free per harness rules)
__device__ float g_xi[2][(size_t)ROWS * G3];   // 2 x 31.5 MB
__device__ float g_h[2][B_][H_];

// ---------------- packed fp32x2 helpers (sm_100+) ----------------
__device__ __forceinline__ unsigned long long pack2f(float lo, float hi) {
    unsigned long long r;
    asm("mov.b64 %0, {%1, %2};" : "=l"(r) : "f"(lo), "f"(hi));
    return r;
}
__device__ __forceinline__ unsigned long long fma2(unsigned long long a,
                                                   unsigned long long b,
                                                   unsigned long long c) {
    unsigned long long d;
    asm("fma.rn.f32x2 %0, %1, %2, %3;" : "=l"(d) : "l"(a), "l"(b), "l"(c));
    return d;
}
__device__ __forceinline__ float2 unpack2f(unsigned long long v) {
    float2 f;
    asm("mov.b64 {%0, %1}, %2;" : "=f"(f.x), "=f"(f.y) : "l"(v));
    return f;
}

// ============================================================================
// Kernel A: xi[row, 0:30] = x[row, 0:130] @ Wih^T + bih   (row = b*T + t)
// 256 threads = 256 rows per block. W pre-packed in SMEM as f32x2 pairs.
// ============================================================================
__global__ __launch_bounds__(TPB) void xi_kernel(
    const float* __restrict__ x,
    const float* __restrict__ Wih,   // [30][130]
    const float* __restrict__ bih,   // [30]
    int gru)
{
    // wshv[k][q]: q=0..7 covers gate pairs (4q,4q+1),(4q+2,4q+3); g>=30 padded 0
    __shared__ ulonglong2 wshv[I_ * 8];
    __shared__ float xs[TPB * (CHUNK + 1)];   // odd stride 27: conflict-free

    const int tid = threadIdx.x;

    for (int idx = tid; idx < I_ * 8; idx += TPB) {
        int k = idx >> 3, q = idx & 7;
        int g = q * 4;
        float v0 = (g + 0 < G3) ? Wih[(g + 0) * I_ + k] : 0.f;
        float v1 = (g + 1 < G3) ? Wih[(g + 1) * I_ + k] : 0.f;
        float v2 = (g + 2 < G3) ? Wih[(g + 2) * I_ + k] : 0.f;
        float v3 = (g + 3 < G3) ? Wih[(g + 3) * I_ + k] : 0.f;
        ulonglong2 e;
        e.x = pack2f(v0, v1);
        e.y = pack2f(v2, v3);
        wshv[idx] = e;
    }

    unsigned long long acc[15];
#pragma unroll
    for (int jj = 0; jj < 15; jj++)
        acc[jj] = pack2f(bih[2 * jj], bih[2 * jj + 1]);

    const size_t row0 = (size_t)blockIdx.x * TPB;
    const float* xrow = x + row0 * I_;

    for (int c = 0; c < 5; c++) {
        // stage x chunk [256 rows][26 k] (coalesced-ish: contiguous 104B runs)
        for (int idx = tid; idx < TPB * CHUNK; idx += TPB) {
            int r = idx / CHUNK, k = idx - r * CHUNK;
            xs[r * (CHUNK + 1) + k] = xrow[(size_t)r * I_ + c * CHUNK + k];
        }
        __syncthreads();

        const float* xb = xs + tid * (CHUNK + 1);
#pragma unroll
        for (int kk = 0; kk < CHUNK; kk++) {
            float xk = xb[kk];
            unsigned long long xp = pack2f(xk, xk);
            const ulonglong2* wp = wshv + (c * CHUNK + kk) * 8;
#pragma unroll
            for (int q = 0; q < 7; q++) {
                ulonglong2 wv = wp[q];                     // ld.shared.v2.u64
                acc[2 * q]     = fma2(wv.x, xp, acc[2 * q]);
                acc[2 * q + 1] = fma2(wv.y, xp, acc[2 * q + 1]);
            }
            ulonglong2 wv = wp[7];
            acc[14] = fma2(wv.x, xp, acc[14]);             // gates 28,29
        }
        __syncthreads();
    }

    float2* out = (float2*)(g_xi[gru] + (row0 + tid) * G3);
#pragma unroll
    for (int jj = 0; jj < 15; jj++)
        out[jj] = unpack2f(acc[jj]);
}

// ============================================================================
// Kernel B: GRU scan. One warp per (gru, batch). Lanes 0..29 each own one
// gate row of Whh; h[0..9] replicated per lane; exchange via shfl.
// ============================================================================
__global__ __launch_bounds__(256) void scan_kernel(
    const float* __restrict__ ruWhh, const float* __restrict__ rubhh,
    const float* __restrict__ enWhh, const float* __restrict__ enbhh)
{
    const int gwarp = (blockIdx.x * blockDim.x + threadIdx.x) >> 5;  // 0..4095
    const int lane  = threadIdx.x & 31;
    const int gru   = gwarp >> 11;
    const int b     = gwarp & (B_ - 1);

    const float* Whh = gru ? enWhh : ruWhh;
    const float* bhh = gru ? enbhh : rubhh;

    float wr[10];
    float bb = 0.f;
    if (lane < G3) {
#pragma unroll
        for (int j = 0; j < 10; j++) wr[j] = Whh[lane * 10 + j];
        bb = bhh[lane];
    } else {
#pragma unroll
        for (int j = 0; j < 10; j++) wr[j] = 0.f;
    }

    float h[10];
#pragma unroll
    for (int j = 0; j < 10; j++) h[j] = 0.f;

    const float* xib = g_xi[gru] + (size_t)b * T_ * G3;

    // prefetch t=0 (keeps L2-hit latency out of the step dependency chain)
    float xv = (lane < G3) ? xib[lane] : 0.f;

    for (int t = 0; t < T_; t++) {
        float xvn = 0.f;
        if (lane < G3 && t + 1 < T_) xvn = xib[(t + 1) * G3 + lane];

        float gh = bb;
#pragma unroll
        for (int j = 0; j < 10; j++) gh = fmaf(wr[j], h[j], gh);

        float a   = xv + gh;
        float sig = __fdividef(1.f, 1.f + __expf(-a));     // r (lanes 0-9), z (10-19)

        // n-lanes (20-29) fetch r from lane-20
        int   src = (lane >= 20 && lane < G3) ? (lane - 20) : lane;
        float r   = __shfl_sync(0xFFFFFFFFu, sig, src);

        float val = sig;
        if (lane >= 20) {
            float narg = xv + r * gh;                       // gh_n includes bhh_n
            float s2   = __fdividef(1.f, 1.f + __expf(-2.f * narg));
            val        = 2.f * s2 - 1.f;                    // tanh
        }

#pragma unroll
        for (int j = 0; j < 10; j++) {
            float z = __shfl_sync(0xFFFFFFFFu, val, 10 + j);
            float n = __shfl_sync(0xFFFFFFFFu, val, 20 + j);
            h[j] = n + z * (h[j] - n);                      // (1-z)*n + z*h
        }
        xv = xvn;
    }

    if (lane == 0) {
#pragma unroll
        for (int j = 0; j < 10; j++) g_h[gru][b][j] = h[j];
    }
}

// ============================================================================
// Kernel C: out[b] = W2 @ (W1 @ concat(ru_h, en_h) + b1) + b2
// ============================================================================
__global__ __launch_bounds__(256) void head_kernel(
    const float* __restrict__ W1, const float* __restrict__ b1,
    const float* __restrict__ W2, const float* __restrict__ b2,
    float* __restrict__ out)
{
    int b = blockIdx.x * blockDim.x + threadIdx.x;
    if (b >= B_) return;

    float hin[20];
#pragma unroll
    for (int j = 0; j < 10; j++) {
        hin[j]      = g_h[0][b][j];
        hin[10 + j] = g_h[1][b][j];
    }
    float accum = b2[0];
#pragma unroll
    for (int d = 0; d < 20; d++) {
        float s = b1[d];
#pragma unroll
        for (int j = 0; j < 20; j++) s = fmaf(W1[d * 20 + j], hin[j], s);
        accum = fmaf(W2[d], s, accum);
    }
    out[b] = accum;
}

// ============================================================================
extern "C" void kernel_launch(void* const* d_in, const int* in_sizes, int n_in,
                              void* d_out, int out_size)
{
    const float* ru     = (const float*)d_in[0];
    const float* en     = (const float*)d_in[1];
    const float* ru_Wih = (const float*)d_in[2];
    const float* ru_Whh = (const float*)d_in[3];
    const float* ru_bih = (const float*)d_in[4];
    const float* ru_bhh = (const float*)d_in[5];
    const float* en_Wih = (const float*)d_in[6];
    const float* en_Whh = (const float*)d_in[7];
    const float* en_bih = (const float*)d_in[8];
    const float* en_bhh = (const float*)d_in[9];
    const float* W1     = (const float*)d_in[10];
    const float* b1     = (const float*)d_in[11];
    const float* W2     = (const float*)d_in[12];
    const float* b2     = (const float*)d_in[13];
    float* out = (float*)d_out;

    xi_kernel<<<ROWS / TPB, TPB>>>(ru, ru_Wih, ru_bih, 0);
    xi_kernel<<<ROWS / TPB, TPB>>>(en, en_Wih, en_bih, 1);
    scan_kernel<<<(2 * B_ * 32) / 256, 256>>>(ru_Whh, ru_bhh, en_Whh, en_bhh);
    head_kernel<<<(B_ + 255) / 256, 256>>>(W1, b1, W2, b2, out);
}

// round 3
// speedup vs baseline: 1.5929x; 1.5929x over previous
#include <cuda_runtime.h>

#define B_    2048
#define T_    128
#define I_    130
#define H_    10
#define G3    30            // 3*H
#define ROWS  (B_ * T_)     // 262144
#define XI_STRIDE 32        // padded row stride for g_xi (128B-aligned rows)
#define CH    13            // 130 = 10 * 13
#define NCH   10
#define XTPB  256
#define XROWS 512           // rows per xi block (2 rows / thread)

// Scratch (static device globals: allocation-free per harness rules)
__device__ float g_xi[2][(size_t)ROWS * XI_STRIDE];   // 2 x 32MB, cols 30/31 unused

// ---------------- packed fp32x2 helpers (sm_100+) ----------------
__device__ __forceinline__ unsigned long long pack2f(float lo, float hi) {
    unsigned long long r;
    asm("mov.b64 %0, {%1, %2};" : "=l"(r) : "f"(lo), "f"(hi));
    return r;
}
__device__ __forceinline__ unsigned long long fma2(unsigned long long a,
                                                   unsigned long long b,
                                                   unsigned long long c) {
    unsigned long long d;
    asm("fma.rn.f32x2 %0, %1, %2, %3;" : "=l"(d) : "l"(a), "l"(b), "l"(c));
    return d;
}

__device__ __forceinline__ float sigf(float a) {
    return __fdividef(1.f, 1.f + __expf(-a));
}

// ============================================================================
// Kernel A: xi[row, 0:30] = x[row, 0:130] @ Wih^T + bih   (row = b*T + t)
// One launch covers both GRUs (blockIdx.y). 256 threads x 2 rows each.
// W pre-packed in SMEM as f32x2 gate-pairs; output padded to stride 32.
// ============================================================================
__global__ __launch_bounds__(XTPB) void xi_kernel(
    const float* __restrict__ ru,  const float* __restrict__ en,
    const float* __restrict__ ruW, const float* __restrict__ enW,
    const float* __restrict__ rub, const float* __restrict__ enb)
{
    const int gru = blockIdx.y;
    const float* __restrict__ x   = gru ? en  : ru;
    const float* __restrict__ Wih = gru ? enW : ruW;
    const float* __restrict__ bih = gru ? enb : rub;

    // wsh[k*8 + q]: f32x2 pairs for gates (4q,4q+1),(4q+2,4q+3); g>=30 padded 0
    __shared__ ulonglong2 wsh[I_ * 8];                 // 16640 B
    __shared__ float xs[XROWS * (CH + 1)];             // 28672 B (stride 14)

    const int tid = threadIdx.x;

    for (int idx = tid; idx < I_ * 8; idx += XTPB) {
        int k = idx >> 3, q = idx & 7, g = q * 4;
        float v0 = (g + 0 < G3) ? Wih[(g + 0) * I_ + k] : 0.f;
        float v1 = (g + 1 < G3) ? Wih[(g + 1) * I_ + k] : 0.f;
        float v2 = (g + 2 < G3) ? Wih[(g + 2) * I_ + k] : 0.f;
        float v3 = (g + 3 < G3) ? Wih[(g + 3) * I_ + k] : 0.f;
        ulonglong2 e;
        e.x = pack2f(v0, v1);
        e.y = pack2f(v2, v3);
        wsh[idx] = e;
    }

    unsigned long long acc0[15], acc1[15];
#pragma unroll
    for (int jj = 0; jj < 15; jj++) {
        unsigned long long bv = pack2f(bih[2 * jj], bih[2 * jj + 1]);
        acc0[jj] = bv;
        acc1[jj] = bv;
    }

    const int row0 = blockIdx.x * XROWS;

    for (int c = 0; c < NCH; c++) {
        // stage x chunk [512 rows][13 k]
        for (int r = tid; r < XROWS; r += XTPB) {
            const float* src = x + (size_t)(row0 + r) * I_ + c * CH;
            float* dst = xs + r * (CH + 1);
#pragma unroll
            for (int kk = 0; kk < CH; kk++) dst[kk] = src[kk];
        }
        __syncthreads();

        const float* xb0 = xs + tid * (CH + 1);
        const float* xb1 = xs + (tid + XTPB) * (CH + 1);
#pragma unroll
        for (int kk = 0; kk < CH; kk++) {
            float x0 = xb0[kk], x1 = xb1[kk];
            unsigned long long xp0 = pack2f(x0, x0);
            unsigned long long xp1 = pack2f(x1, x1);
            const ulonglong2* wp = wsh + (c * CH + kk) * 8;
#pragma unroll
            for (int q = 0; q < 7; q++) {
                ulonglong2 wv = wp[q];                 // uniform LDS.128 broadcast
                acc0[2 * q]     = fma2(wv.x, xp0, acc0[2 * q]);
                acc0[2 * q + 1] = fma2(wv.y, xp0, acc0[2 * q + 1]);
                acc1[2 * q]     = fma2(wv.x, xp1, acc1[2 * q]);
                acc1[2 * q + 1] = fma2(wv.y, xp1, acc1[2 * q + 1]);
            }
            ulonglong2 wv = wp[7];
            acc0[14] = fma2(wv.x, xp0, acc0[14]);      // gates 28,29
            acc1[14] = fma2(wv.x, xp1, acc1[14]);
        }
        __syncthreads();
    }

    // store: 7x STG.128 + 1x STG.64 per row (row base 128B-aligned)
    {
        float* o0 = g_xi[gru] + (size_t)(row0 + tid) * XI_STRIDE;
        float* o1 = g_xi[gru] + (size_t)(row0 + tid + XTPB) * XI_STRIDE;
        ulonglong2* v0 = (ulonglong2*)o0;
        ulonglong2* v1 = (ulonglong2*)o1;
#pragma unroll
        for (int p = 0; p < 7; p++) {
            ulonglong2 e0, e1;
            e0.x = acc0[2 * p]; e0.y = acc0[2 * p + 1];
            e1.x = acc1[2 * p]; e1.y = acc1[2 * p + 1];
            v0[p] = e0;
            v1[p] = e1;
        }
        // gates 28,29 live at float offset 28 == u64 index 14 (R2 bug: was [7])
        ((unsigned long long*)o0)[14] = acc0[14];
        ((unsigned long long*)o1)[14] = acc1[14];
    }
}

// ============================================================================
// Kernel B: GRU scan + fused head MLP.
// Block = 256 threads = 8 warps = 4 batches x 2 GRUs. Warp lanes 0..29 own
// one gate row of Whh; 13 shuffles per step (was 21).
// ============================================================================
__global__ __launch_bounds__(256) void scan_head_kernel(
    const float* __restrict__ ruWhh, const float* __restrict__ rubhh,
    const float* __restrict__ enWhh, const float* __restrict__ enbhh,
    const float* __restrict__ W1, const float* __restrict__ b1,
    const float* __restrict__ W2, const float* __restrict__ b2,
    float* __restrict__ out)
{
    __shared__ float sh[4][2][10];

    const int w    = threadIdx.x >> 5;
    const int lane = threadIdx.x & 31;
    const int pair = w >> 1;           // 0..3 : batch within block
    const int gru  = w & 1;
    const int b    = blockIdx.x * 4 + pair;
    const int lm   = lane % 10;

    const float* Whh = gru ? enWhh : ruWhh;
    const float* bhh = gru ? enbhh : rubhh;

    float wr[10];
    float bb = 0.f;
    if (lane < G3) {
#pragma unroll
        for (int j = 0; j < 10; j++) wr[j] = Whh[lane * 10 + j];
        bb = bhh[lane];
    } else {
#pragma unroll
        for (int j = 0; j < 10; j++) wr[j] = 0.f;
    }

    float h[10];
#pragma unroll
    for (int j = 0; j < 10; j++) h[j] = 0.f;
    float hd = 0.f;                      // distributed copy: hd == h[lane-20] on n-lanes

    const float* __restrict__ xib = g_xi[gru] + (size_t)b * T_ * XI_STRIDE;

    // depth-2 prefetch to cover L2 latency
    float xv  = (lane < G3) ? xib[lane] : 0.f;
    float xv1 = (lane < G3) ? xib[XI_STRIDE + lane] : 0.f;

    const int rsrc = (lane >= 20) ? (lane - 20) : lane;

    for (int t = 0; t < T_; t++) {
        float xv2 = 0.f;
        if (lane < G3 && t + 2 < T_) xv2 = xib[(size_t)(t + 2) * XI_STRIDE + lane];

        float gh = bb;
#pragma unroll
        for (int j = 0; j < 10; j++) gh = fmaf(wr[j], h[j], gh);

        float a   = xv + gh;
        float sig = sigf(a);                               // r (0-9), z (10-19)

        float r    = __shfl_sync(0xFFFFFFFFu, sig, rsrc);  // n-lanes get r_j
        float narg = fmaf(r, gh, xv);
        float s2   = sigf(2.f * narg);
        float tanhv = fmaf(2.f, s2, -1.f);
        float val  = (lane >= 20) ? tanhv : sig;           // lanes 20-29: n

        float zed  = __shfl_sync(0xFFFFFFFFu, val, 10 + lm);  // z_{lm}
        float hnew = val + zed * (hd - val);               // valid on lanes 20-29

        hd = __shfl_sync(0xFFFFFFFFu, hnew, 20 + lm);
#pragma unroll
        for (int j = 0; j < 10; j++)
            h[j] = __shfl_sync(0xFFFFFFFFu, hnew, 20 + j);

        xv  = xv1;
        xv1 = xv2;
    }

    if (lane == 0) {
#pragma unroll
        for (int j = 0; j < 10; j++) sh[pair][gru][j] = h[j];
    }
    __syncthreads();

    // head: warps 0..3, one batch each; lanes 0..19 compute h1[d], warp-reduce
    if (w < 4) {
        float s = 0.f;
        if (lane < 20) {
            float acc = b1[lane];
            const float* w1r = W1 + lane * 20;
#pragma unroll
            for (int j = 0; j < 10; j++) acc = fmaf(w1r[j], sh[w][0][j], acc);
#pragma unroll
            for (int j = 0; j < 10; j++) acc = fmaf(w1r[10 + j], sh[w][1][j], acc);
            s = acc * W2[lane];
        }
#pragma unroll
        for (int off = 16; off; off >>= 1)
            s += __shfl_xor_sync(0xFFFFFFFFu, s, off);
        if (lane == 0) out[blockIdx.x * 4 + w] = s + b2[0];
    }
}

// ============================================================================
extern "C" void kernel_launch(void* const* d_in, const int* in_sizes, int n_in,
                              void* d_out, int out_size)
{
    const float* ru     = (const float*)d_in[0];
    const float* en     = (const float*)d_in[1];
    const float* ru_Wih = (const float*)d_in[2];
    const float* ru_Whh = (const float*)d_in[3];
    const float* ru_bih = (const float*)d_in[4];
    const float* ru_bhh = (const float*)d_in[5];
    const float* en_Wih = (const float*)d_in[6];
    const float* en_Whh = (const float*)d_in[7];
    const float* en_bih = (const float*)d_in[8];
    const float* en_bhh = (const float*)d_in[9];
    const float* W1     = (const float*)d_in[10];
    const float* b1     = (const float*)d_in[11];
    const float* W2     = (const float*)d_in[12];
    const float* b2     = (const float*)d_in[13];
    float* out = (float*)d_out;

    dim3 gx(ROWS / XROWS, 2);   // 512 x 2
    xi_kernel<<<gx, XTPB>>>(ru, en, ru_Wih, en_Wih, ru_bih, en_bih);
    scan_head_kernel<<<B_ / 4, 256>>>(ru_Whh, ru_bhh, en_Whh, en_bhh,
                                      W1, b1, W2, b2, out);
}